// round 14
// baseline (speedup 1.0000x reference)
#include <cuda_runtime.h>
#include <cuda_fp16.h>
#include <cstdint>
#include <cstddef>

// ---------------- problem sizes ----------------
#define MDIM 8192
#define NDIM 4096
#define KDIM 4096
#define MT 128          // CTA tile M
#define NT 128          // CTA tile N
#define KC 64           // K elements per chunk (fp16 -> 128B rows)
#define NCHUNK (KDIM / KC)          // 64
#define NTILES ((MDIM / MT) * (NDIM / NT))  // 2048
#define GRIDSZ 296                  // 148 SMs x 2 CTAs (persistent)
#define STAGES 3
#define A_TILE 16384                // 128 rows x 128B
#define B_TILE 16384                // 128 rows x 128B
#define STAGE_BYTES (A_TILE + B_TILE)       // 32768
#define SMEM_BYTES (STAGES * STAGE_BYTES)   // 98304 -> 2 CTAs/SM

// ---------------- device scratch (no allocation allowed) ----------------
__device__ __align__(128) __half g_X[(size_t)MDIM * KDIM];
__device__ __align__(128) __half g_W[(size_t)NDIM * KDIM];

// ---------------- PTX helpers (base sm_103 target only) -------------------
static __device__ __forceinline__ uint32_t smem_u32(const void* p) {
    uint32_t a;
    asm("{ .reg .u64 t; cvta.to.shared.u64 t, %1; cvt.u32.u64 %0, t; }" : "=r"(a) : "l"(p));
    return a;
}

#define CP16(dst, src) \
    asm volatile("cp.async.cg.shared.global [%0], [%1], 16;" :: "r"((uint32_t)(dst)), "l"(src) : "memory")
#define CP_COMMIT() asm volatile("cp.async.commit_group;" ::: "memory")
#define CP_WAIT(n)  asm volatile("cp.async.wait_group %0;" :: "n"(n) : "memory")

#define LDSM4(r0, r1, r2, r3, addr) \
    asm volatile("ldmatrix.sync.aligned.m8n8.x4.shared.b16 {%0,%1,%2,%3}, [%4];" \
                 : "=r"(r0), "=r"(r1), "=r"(r2), "=r"(r3) : "r"(addr))

// f16 MMA, fp32 accumulate: D[16x8] += A[16x16] * B[16x8]
#define MMA_F16(d, a0, a1, a2, a3, b0, b1) \
    asm volatile("mma.sync.aligned.m16n8k16.row.col.f32.f16.f16.f32 " \
                 "{%0,%1,%2,%3}, {%4,%5,%6,%7}, {%8,%9}, {%0,%1,%2,%3};" \
                 : "+f"((d)[0]), "+f"((d)[1]), "+f"((d)[2]), "+f"((d)[3]) \
                 : "r"(a0), "r"(a1), "r"(a2), "r"(a3), "r"(b0), "r"(b1))

// ---------------- fused prepass: x fp32->fp16, w int32->fp16 --------------
// 8 elements per thread per iteration: two 16B loads -> one 16B store.
#define NX8 ((size_t)MDIM * KDIM / 8)
#define NW8 ((size_t)NDIM * KDIM / 8)
__global__ void __launch_bounds__(256) cvt_kernel(const float* __restrict__ x,
                                                  const int* __restrict__ w) {
    const float4* __restrict__ x4 = (const float4*)x;
    const int4* __restrict__ w4 = (const int4*)w;
    uint4* __restrict__ dx = (uint4*)g_X;
    uint4* __restrict__ dw = (uint4*)g_W;
    const size_t total = NX8 + NW8;
    size_t stride = (size_t)gridDim.x * blockDim.x;
    for (size_t i = (size_t)blockIdx.x * blockDim.x + threadIdx.x; i < total; i += stride) {
        uint4 p;
        if (i < NX8) {
            float4 v0 = x4[2 * i];
            float4 v1 = x4[2 * i + 1];
            p.x = (uint32_t)__half_as_ushort(__float2half_rn(v0.x)) |
                  ((uint32_t)__half_as_ushort(__float2half_rn(v0.y)) << 16);
            p.y = (uint32_t)__half_as_ushort(__float2half_rn(v0.z)) |
                  ((uint32_t)__half_as_ushort(__float2half_rn(v0.w)) << 16);
            p.z = (uint32_t)__half_as_ushort(__float2half_rn(v1.x)) |
                  ((uint32_t)__half_as_ushort(__float2half_rn(v1.y)) << 16);
            p.w = (uint32_t)__half_as_ushort(__float2half_rn(v1.z)) |
                  ((uint32_t)__half_as_ushort(__float2half_rn(v1.w)) << 16);
            dx[i] = p;
        } else {
            const size_t j = i - NX8;
            int4 v0 = w4[2 * j];
            int4 v1 = w4[2 * j + 1];
            p.x = (uint32_t)__half_as_ushort(__int2half_rn(v0.x)) |
                  ((uint32_t)__half_as_ushort(__int2half_rn(v0.y)) << 16);
            p.y = (uint32_t)__half_as_ushort(__int2half_rn(v0.z)) |
                  ((uint32_t)__half_as_ushort(__int2half_rn(v0.w)) << 16);
            p.z = (uint32_t)__half_as_ushort(__int2half_rn(v1.x)) |
                  ((uint32_t)__half_as_ushort(__int2half_rn(v1.y)) << 16);
            p.w = (uint32_t)__half_as_ushort(__int2half_rn(v1.z)) |
                  ((uint32_t)__half_as_ushort(__int2half_rn(v1.w)) << 16);
            dw[j] = p;
        }
    }
}

// ---------------- main GEMM: persistent CTAs, continuous pipeline ---------
// 128 threads = 4 warps; warp tile 64x64; 2 CTAs/SM; grid = 296 persistent
// CTAs each walking tiles t = bid, bid+296, ... The 3-stage cp.async pipeline
// runs over the FLAT chunk sequence across tiles (chunks 62/63 of tile j load
// chunks 0/1 of tile j+GRIDSZ), so prologue stalls and epilogue exposure are
// hidden under the in-flight loads + prefetched fragments of the next tile.
__global__ void __launch_bounds__(128, 2) qgemm_kernel(
    const float* __restrict__ scale,
    const float* __restrict__ bias,
    float* __restrict__ out
) {
    extern __shared__ char smem[];
    const uint32_t sbase = smem_u32(smem);
    const int tid = threadIdx.x;

    const int lane = tid & 31;
    const int wid = tid >> 5;
    const int wm = wid & 1;      // M half (64 rows)
    const int wn = wid >> 1;     // N half (64 cols)

    // ldmatrix address components
    const int rA = 64 * wm + (lane & 7) + ((lane >> 3) & 1) * 8;
    const int kaddA = ((lane >> 4) & 1) * 16;
    const uint32_t xmA = (uint32_t)((lane & 7) << 4);
    const int nrb = 64 * wn + (lane & 7) + ((lane >> 4) & 1) * 8;
    const int kaddB = ((lane >> 3) & 1) * 16;
    const uint32_t xmB = (uint32_t)((lane & 7) << 4);
    const uint32_t kA0 = ((uint32_t)kaddA) ^ xmA;
    const uint32_t kB0 = ((uint32_t)kaddB) ^ xmB;

    float acc[4][8][4];
    #pragma unroll
    for (int a = 0; a < 4; ++a)
        #pragma unroll
        for (int b = 0; b < 8; ++b)
            #pragma unroll
            for (int c = 0; c < 4; ++c) acc[a][b][c] = 0.0f;

    // tile id -> gmem byte-bases (row stride = KDIM*2 bytes = 1<<13)
    auto tileX = [&](int t) -> const char* {
        return (const char*)g_X + (((size_t)(t >> 5) * MT) << 13);
    };
    auto tileW = [&](int t) -> const char* {
        return (const char*)g_W + (((size_t)(t & 31) * NT) << 13);
    };

    // ---- stage loader: A 16KB + B 16KB, 8 granule-pairs/thread ----
    auto load_stage = [&](int stg, const char* pX, const char* pW, int c) {
        const uint32_t st = sbase + (uint32_t)stg * STAGE_BYTES;
        const uint32_t ko = (uint32_t)c << 7;       // c * 128 bytes along K
        #pragma unroll
        for (int i = 0; i < 8; ++i) {               // A + B: rows 0..127 each
            const int g = tid + i * 128;
            const int row = g >> 3;
            const int col = (g & 7) << 4;
            const uint32_t soff = (uint32_t)(row * 128) + ((uint32_t)col ^ (uint32_t)((row & 7) << 4));
            const size_t goff = ((size_t)row << 13) + ko + col;
            CP16(st + soff,          pX + goff);
            CP16(st + A_TILE + soff, pW + goff);
        }
    };

    uint32_t af[4][4];
    uint32_t bf[4][4];

    // ks0 fragment loader from a given stage base
    auto ldsm_ks0 = [&](uint32_t st) {
        const uint32_t aA = st + (uint32_t)(rA * 128);
        const uint32_t aB = st + A_TILE + (uint32_t)(nrb * 128);
        #pragma unroll
        for (int mb = 0; mb < 4; ++mb)
            LDSM4(af[mb][0], af[mb][1], af[mb][2], af[mb][3],
                  aA + (uint32_t)(mb * 16 * 128) + kA0);
        #pragma unroll
        for (int p = 0; p < 4; ++p)
            LDSM4(bf[p][0], bf[p][1], bf[p][2], bf[p][3],
                  aB + (uint32_t)(p * 16 * 128) + kB0);
    };

    int t = blockIdx.x;                  // current tile
    if (t >= NTILES) return;

    // ---- prologue: first tile's chunks 0,1; prefetch ks0 of chunk 0 ----
    load_stage(0, tileX(t), tileW(t), 0); CP_COMMIT();
    load_stage(1, tileX(t), tileW(t), 1); CP_COMMIT();
    CP_WAIT(1);
    __syncthreads();
    ldsm_ks0(sbase);

    int s_cur = 0;          // stage of current flat chunk
    int s_nxt = 2;          // stage to fill with flat chunk +2

    while (true) {
        const char* pXc = tileX(t);
        const char* pWc = tileW(t);
        const bool hasnext = (t + GRIDSZ) < NTILES;

        for (int c = 0; c < NCHUNK; ++c) {
            const uint32_t st = sbase + (uint32_t)s_cur * STAGE_BYTES;
            const uint32_t aA = st + (uint32_t)(rA * 128);
            const uint32_t aB = st + A_TILE + (uint32_t)(nrb * 128);

            // ---- ks0 MMAs from prefetched fragments
            #pragma unroll
            for (int mb = 0; mb < 4; ++mb) {
                #pragma unroll
                for (int nt = 0; nt < 8; ++nt) {
                    const uint32_t b0 = bf[nt >> 1][(nt & 1) * 2];
                    const uint32_t b1 = bf[nt >> 1][(nt & 1) * 2 + 1];
                    MMA_F16(acc[mb][nt], af[mb][0], af[mb][1], af[mb][2], af[mb][3], b0, b1);
                }
            }

            // ---- produce flat chunk +2 under the ks0 MMA backlog
            if (c + 2 < NCHUNK) {
                load_stage(s_nxt, pXc, pWc, c + 2);
            } else if (hasnext) {
                load_stage(s_nxt, tileX(t + GRIDSZ), tileW(t + GRIDSZ), c + 2 - NCHUNK);
            }
            CP_COMMIT();

            // ---- k-steps 1..3
            #pragma unroll
            for (int ks = 1; ks < 4; ++ks) {
                const uint32_t kA = ((uint32_t)(ks * 32 + kaddA)) ^ xmA;
                const uint32_t kB = ((uint32_t)(ks * 32 + kaddB)) ^ xmB;
                #pragma unroll
                for (int mb = 0; mb < 4; ++mb)
                    LDSM4(af[mb][0], af[mb][1], af[mb][2], af[mb][3],
                          aA + (uint32_t)(mb * 16 * 128) + kA);
                #pragma unroll
                for (int p = 0; p < 4; ++p)
                    LDSM4(bf[p][0], bf[p][1], bf[p][2], bf[p][3],
                          aB + (uint32_t)(p * 16 * 128) + kB);
                #pragma unroll
                for (int mb = 0; mb < 4; ++mb) {
                    #pragma unroll
                    for (int nt = 0; nt < 8; ++nt) {
                        const uint32_t b0 = bf[nt >> 1][(nt & 1) * 2];
                        const uint32_t b1 = bf[nt >> 1][(nt & 1) * 2 + 1];
                        MMA_F16(acc[mb][nt], af[mb][0], af[mb][1], af[mb][2], af[mb][3], b0, b1);
                    }
                }
            }

            // ---- end of flat chunk: next flat chunk is resident; prefetch it
            CP_WAIT(1);
            __syncthreads();
            s_cur = (s_cur == 2) ? 0 : s_cur + 1;
            s_nxt = (s_nxt == 2) ? 0 : s_nxt + 1;
            if (c + 1 < NCHUNK || hasnext)
                ldsm_ks0(sbase + (uint32_t)s_cur * STAGE_BYTES);
        }

        // ---- epilogue for tile t (next tile's loads fly + frags prefetched)
        {
            const int m0 = (t >> 5) * MT;
            const int n0 = (t & 31) * NT;
            const int ncol = n0 + 64 * wn + 2 * (lane & 3);
            const float* scn = scale + ncol;
            const float* bin = bias + ncol;
            #pragma unroll
            for (int mb = 0; mb < 4; ++mb) {
                const int mr0 = m0 + 64 * wm + 16 * mb + (lane >> 2);
                const int mr1 = mr0 + 8;
                float* o0 = out + (size_t)mr0 * NDIM + ncol;
                float* o1 = out + (size_t)mr1 * NDIM + ncol;
                #pragma unroll
                for (int nt = 0; nt < 8; ++nt) {
                    const float2 ws = *(const float2*)(scn + 8 * nt);
                    const float2 bb = *(const float2*)(bin + 8 * nt);
                    float2 v0, v1;
                    v0.x = ws.x * acc[mb][nt][0] + bb.x;
                    v0.y = ws.y * acc[mb][nt][1] + bb.y;
                    v1.x = ws.x * acc[mb][nt][2] + bb.x;
                    v1.y = ws.y * acc[mb][nt][3] + bb.y;
                    *(float2*)(o0 + 8 * nt) = v0;
                    *(float2*)(o1 + 8 * nt) = v1;
                    acc[mb][nt][0] = 0.0f;
                    acc[mb][nt][1] = 0.0f;
                    acc[mb][nt][2] = 0.0f;
                    acc[mb][nt][3] = 0.0f;
                }
            }
        }

        if (!hasnext) break;
        t += GRIDSZ;
    }
}

// ---------------- launcher ----------------
extern "C" void kernel_launch(void* const* d_in, const int* in_sizes, int n_in,
                              void* d_out, int out_size) {
    const float* x     = (const float*)d_in[0];
    const int*   w     = (const int*)d_in[1];
    const float* scale = (const float*)d_in[2];
    const float* bias  = (const float*)d_in[3];
    float* out = (float*)d_out;

    cudaFuncSetAttribute(qgemm_kernel, cudaFuncAttributeMaxDynamicSharedMemorySize, SMEM_BYTES);

    cvt_kernel<<<4096, 256>>>(x, w);

    qgemm_kernel<<<GRIDSZ, 128, SMEM_BYTES>>>(scale, bias, out);
}

// round 15
// speedup vs baseline: 1.0147x; 1.0147x over previous
#include <cuda_runtime.h>
#include <cuda_fp16.h>
#include <cstdint>
#include <cstddef>

// ---------------- problem sizes ----------------
#define MDIM 8192
#define NDIM 4096
#define KDIM 4096
#define MT 128          // CTA tile M
#define NT 128          // CTA tile N
#define KC 64           // K elements per chunk (fp16 -> 128B rows)
#define NCHUNK (KDIM / KC)          // 64
#define STAGES 3
#define A_TILE 16384                // 128 rows x 128B
#define B_TILE 16384                // 128 rows x 128B
#define STAGE_BYTES (A_TILE + B_TILE)       // 32768
#define SMEM_BYTES (1024 + STAGES * STAGE_BYTES)   // 99328 -> 2 CTAs/SM

// ---------------- device scratch (no allocation allowed) ----------------
__device__ __align__(128) __half g_X[(size_t)MDIM * KDIM];
__device__ __align__(128) __half g_W[(size_t)NDIM * KDIM];

// ---------------- PTX helpers (base sm_103 target only) -------------------
static __device__ __forceinline__ uint32_t smem_u32(const void* p) {
    uint32_t a;
    asm("{ .reg .u64 t; cvta.to.shared.u64 t, %1; cvt.u32.u64 %0, t; }" : "=r"(a) : "l"(p));
    return a;
}

#define CP16(dst, src) \
    asm volatile("cp.async.cg.shared.global [%0], [%1], 16;" :: "r"((uint32_t)(dst)), "l"(src) : "memory")

// arrive on mbarrier when this thread's prior cp.asyncs have completed
#define CP_ARRIVE(mbar) \
    asm volatile("cp.async.mbarrier.arrive.noinc.shared.b64 [%0];" :: "r"((uint32_t)(mbar)) : "memory")

#define MBARRIER_INIT(addr, count) \
    asm volatile("mbarrier.init.shared.b64 [%0], %1;" :: "r"((uint32_t)(addr)), "r"((uint32_t)(count)) : "memory")

#define MBARRIER_ARRIVE(addr) \
    asm volatile("mbarrier.arrive.shared.b64 _, [%0];" :: "r"((uint32_t)(addr)) : "memory")

#define MBARRIER_WAIT_PARITY(mbar_smem_addr, phase_parity) do { \
    uint32_t _mbar = (uint32_t)(mbar_smem_addr); \
    uint32_t _parity = (uint32_t)(phase_parity); \
    uint32_t _done; \
    asm volatile( \
        "{\n\t" \
        ".reg .pred p;\n\t" \
        "mbarrier.try_wait.parity.acquire.cta.shared::cta.b64 p, [%1], %2;\n\t" \
        "selp.b32 %0, 1, 0, p;\n\t" \
        "}" \
        : "=r"(_done) : "r"(_mbar), "r"(_parity) : "memory"); \
    if (!_done) { \
        asm volatile( \
            "{\n\t" \
            ".reg .pred P1;\n\t" \
            "WAIT_LOOP_%=:\n\t" \
            "mbarrier.try_wait.parity.acquire.cta.shared::cta.b64 P1, [%0], %1, 0x989680;\n\t" \
            "@P1 bra.uni WAIT_DONE_%=;\n\t" \
            "bra.uni WAIT_LOOP_%=;\n\t" \
            "WAIT_DONE_%=:\n\t" \
            "}" \
            :: "r"(_mbar), "r"(_parity) : "memory"); \
    } \
} while (0)

#define LDSM4(r0, r1, r2, r3, addr) \
    asm volatile("ldmatrix.sync.aligned.m8n8.x4.shared.b16 {%0,%1,%2,%3}, [%4];" \
                 : "=r"(r0), "=r"(r1), "=r"(r2), "=r"(r3) : "r"(addr))

// f16 MMA, fp32 accumulate: D[16x8] += A[16x16] * B[16x8]
#define MMA_F16(d, a0, a1, a2, a3, b0, b1) \
    asm volatile("mma.sync.aligned.m16n8k16.row.col.f32.f16.f16.f32 " \
                 "{%0,%1,%2,%3}, {%4,%5,%6,%7}, {%8,%9}, {%0,%1,%2,%3};" \
                 : "+f"((d)[0]), "+f"((d)[1]), "+f"((d)[2]), "+f"((d)[3]) \
                 : "r"(a0), "r"(a1), "r"(a2), "r"(a3), "r"(b0), "r"(b1))

// ---------------- fused prepass: x fp32->fp16, w int32->fp16 --------------
// 8 elements per thread per iteration: two 16B loads -> one 16B store.
#define NX8 ((size_t)MDIM * KDIM / 8)
#define NW8 ((size_t)NDIM * KDIM / 8)
__global__ void __launch_bounds__(256) cvt_kernel(const float* __restrict__ x,
                                                  const int* __restrict__ w) {
    const float4* __restrict__ x4 = (const float4*)x;
    const int4* __restrict__ w4 = (const int4*)w;
    uint4* __restrict__ dx = (uint4*)g_X;
    uint4* __restrict__ dw = (uint4*)g_W;
    const size_t total = NX8 + NW8;
    size_t stride = (size_t)gridDim.x * blockDim.x;
    for (size_t i = (size_t)blockIdx.x * blockDim.x + threadIdx.x; i < total; i += stride) {
        uint4 p;
        if (i < NX8) {
            float4 v0 = x4[2 * i];
            float4 v1 = x4[2 * i + 1];
            p.x = (uint32_t)__half_as_ushort(__float2half_rn(v0.x)) |
                  ((uint32_t)__half_as_ushort(__float2half_rn(v0.y)) << 16);
            p.y = (uint32_t)__half_as_ushort(__float2half_rn(v0.z)) |
                  ((uint32_t)__half_as_ushort(__float2half_rn(v0.w)) << 16);
            p.z = (uint32_t)__half_as_ushort(__float2half_rn(v1.x)) |
                  ((uint32_t)__half_as_ushort(__float2half_rn(v1.y)) << 16);
            p.w = (uint32_t)__half_as_ushort(__float2half_rn(v1.z)) |
                  ((uint32_t)__half_as_ushort(__float2half_rn(v1.w)) << 16);
            dx[i] = p;
        } else {
            const size_t j = i - NX8;
            int4 v0 = w4[2 * j];
            int4 v1 = w4[2 * j + 1];
            p.x = (uint32_t)__half_as_ushort(__int2half_rn(v0.x)) |
                  ((uint32_t)__half_as_ushort(__int2half_rn(v0.y)) << 16);
            p.y = (uint32_t)__half_as_ushort(__int2half_rn(v0.z)) |
                  ((uint32_t)__half_as_ushort(__int2half_rn(v0.w)) << 16);
            p.z = (uint32_t)__half_as_ushort(__int2half_rn(v1.x)) |
                  ((uint32_t)__half_as_ushort(__int2half_rn(v1.y)) << 16);
            p.w = (uint32_t)__half_as_ushort(__int2half_rn(v1.z)) |
                  ((uint32_t)__half_as_ushort(__int2half_rn(v1.w)) << 16);
            dw[j] = p;
        }
    }
}

// ---------------- main GEMM: mma.sync f16 (f32 acc), mbarrier pipeline ----
// 128 threads = 4 warps; warp tile 64x64; 2 CTAs/SM. Per-stage full/empty
// mbarriers (count 128) replace CP_WAIT/__syncthreads so warps drift up to a
// chunk instead of re-aligning at every boundary; cross-chunk ks0 fragment
// prefetch keeps the tensor pipe fed across the boundary.
__global__ void __launch_bounds__(128, 2) qgemm_kernel(
    const float* __restrict__ scale,
    const float* __restrict__ bias,
    float* __restrict__ out
) {
    extern __shared__ char smem[];
    const uint32_t sbase = smem_u32(smem);
    const int tid = threadIdx.x;
    const int m0 = blockIdx.y * MT;
    const int n0 = blockIdx.x * NT;

    // mbarriers: full[s] at sbase + s*8, empty[s] at sbase + 24 + s*8
    const uint32_t mb_full  = sbase;
    const uint32_t mb_empty = sbase + 24;
    const uint32_t tiles    = sbase + 1024;

    if (tid == 0) {
        #pragma unroll
        for (int s = 0; s < STAGES; ++s) {
            MBARRIER_INIT(mb_full + s * 8, 128);    // cp.async noinc arrives
            MBARRIER_INIT(mb_empty + s * 8, 128);   // per-thread read-done arrives
        }
    }
    __syncthreads();

    const int lane = tid & 31;
    const int wid = tid >> 5;
    const int wm = wid & 1;      // M half (64 rows)
    const int wn = wid >> 1;     // N half (64 cols)

    // gmem byte-bases (row stride = KDIM * 2 bytes = 8192 = 1<<13)
    const char* pX = (const char*)g_X + ((size_t)m0 << 13);
    const char* pW = (const char*)g_W + ((size_t)n0 << 13);

    // ldmatrix address components
    const int rA = 64 * wm + (lane & 7) + ((lane >> 3) & 1) * 8;
    const int kaddA = ((lane >> 4) & 1) * 16;
    const uint32_t xmA = (uint32_t)((lane & 7) << 4);
    const int nrb = 64 * wn + (lane & 7) + ((lane >> 4) & 1) * 8;
    const int kaddB = ((lane >> 3) & 1) * 16;
    const uint32_t xmB = (uint32_t)((lane & 7) << 4);
    const uint32_t kA0 = ((uint32_t)kaddA) ^ xmA;
    const uint32_t kB0 = ((uint32_t)kaddB) ^ xmB;

    float acc[4][8][4];
    #pragma unroll
    for (int a = 0; a < 4; ++a)
        #pragma unroll
        for (int b = 0; b < 8; ++b)
            #pragma unroll
            for (int c = 0; c < 4; ++c) acc[a][b][c] = 0.0f;

    // ---- stage loader: A 16KB + B 16KB, 8 granule-pairs/thread ----
    auto load_stage = [&](int stg, int c) {
        const uint32_t st = tiles + (uint32_t)stg * STAGE_BYTES;
        const uint32_t ko = (uint32_t)c << 7;       // c * 128 bytes along K
        #pragma unroll
        for (int i = 0; i < 8; ++i) {               // A + B: rows 0..127 each
            const int g = tid + i * 128;
            const int row = g >> 3;
            const int col = (g & 7) << 4;
            const uint32_t soff = (uint32_t)(row * 128) + ((uint32_t)col ^ (uint32_t)((row & 7) << 4));
            const size_t goff = ((size_t)row << 13) + ko + col;
            CP16(st + soff,          pX + goff);
            CP16(st + A_TILE + soff, pW + goff);
        }
    };

    uint32_t af[4][4];
    uint32_t bf[4][4];

    // ks0 fragment loader from a given stage base
    auto ldsm_ks0 = [&](uint32_t st) {
        const uint32_t aA = st + (uint32_t)(rA * 128);
        const uint32_t aB = st + A_TILE + (uint32_t)(nrb * 128);
        #pragma unroll
        for (int mb = 0; mb < 4; ++mb)
            LDSM4(af[mb][0], af[mb][1], af[mb][2], af[mb][3],
                  aA + (uint32_t)(mb * 16 * 128) + kA0);
        #pragma unroll
        for (int p = 0; p < 4; ++p)
            LDSM4(bf[p][0], bf[p][1], bf[p][2], bf[p][3],
                  aB + (uint32_t)(p * 16 * 128) + kB0);
    };

    // ---- prologue: chunks 0,1 into stages 0,1; prefetch ks0 of chunk 0 ----
    load_stage(0, 0); CP_ARRIVE(mb_full + 0 * 8);
    load_stage(1, 1); CP_ARRIVE(mb_full + 1 * 8);
    MBARRIER_WAIT_PARITY(mb_full + 0 * 8, 0);
    ldsm_ks0(tiles);

    // ---- mainloop ----
    // consumer: chunk c uses stage s_cur=c%3; full parity fp=(c/3)&1. The
    // full-wait for chunk c happens at the END of iteration c-1 (prefetch).
    // producer: iteration c loads chunk c+2 into s_p=(c+2)%3 after waiting
    // empty[s_p] parity ep (ep starts 1: vacuous first wait, flips on wrap).
    int s_cur = 0, fp = 0;
    int s_p = 2, ep = 1;
    for (int c = 0; c < NCHUNK; ++c) {
        const uint32_t st = tiles + (uint32_t)s_cur * STAGE_BYTES;
        const uint32_t aA = st + (uint32_t)(rA * 128);
        const uint32_t aB = st + A_TILE + (uint32_t)(nrb * 128);

        // ---- ks0 MMAs from prefetched fragments (pipe fills immediately)
        #pragma unroll
        for (int mb = 0; mb < 4; ++mb) {
            #pragma unroll
            for (int nt = 0; nt < 8; ++nt) {
                const uint32_t b0 = bf[nt >> 1][(nt & 1) * 2];
                const uint32_t b1 = bf[nt >> 1][(nt & 1) * 2 + 1];
                MMA_F16(acc[mb][nt], af[mb][0], af[mb][1], af[mb][2], af[mb][3], b0, b1);
            }
        }

        // ---- produce chunk c+2 under the ks0 MMA backlog
        if (c + 2 < NCHUNK) {
            MBARRIER_WAIT_PARITY(mb_empty + s_p * 8, ep);
            load_stage(s_p, c + 2);
            CP_ARRIVE(mb_full + s_p * 8);
        }

        // ---- k-steps 1..3
        #pragma unroll
        for (int ks = 1; ks < 4; ++ks) {
            const uint32_t kA = ((uint32_t)(ks * 32 + kaddA)) ^ xmA;
            const uint32_t kB = ((uint32_t)(ks * 32 + kaddB)) ^ xmB;
            #pragma unroll
            for (int mb = 0; mb < 4; ++mb)
                LDSM4(af[mb][0], af[mb][1], af[mb][2], af[mb][3],
                      aA + (uint32_t)(mb * 16 * 128) + kA);
            #pragma unroll
            for (int p = 0; p < 4; ++p)
                LDSM4(bf[p][0], bf[p][1], bf[p][2], bf[p][3],
                      aB + (uint32_t)(p * 16 * 128) + kB);
            #pragma unroll
            for (int mb = 0; mb < 4; ++mb) {
                #pragma unroll
                for (int nt = 0; nt < 8; ++nt) {
                    const uint32_t b0 = bf[nt >> 1][(nt & 1) * 2];
                    const uint32_t b1 = bf[nt >> 1][(nt & 1) * 2 + 1];
                    MMA_F16(acc[mb][nt], af[mb][0], af[mb][1], af[mb][2], af[mb][3], b0, b1);
                }
            }
        }

        // ---- reads of s_cur done: release it, then prefetch next chunk's ks0
        MBARRIER_ARRIVE(mb_empty + s_cur * 8);
        s_cur = (s_cur == 2) ? 0 : s_cur + 1;
        if (s_cur == 0) fp ^= 1;
        s_p = (s_p == 2) ? 0 : s_p + 1;
        if (s_p == 0) ep ^= 1;
        if (c + 1 < NCHUNK) {
            MBARRIER_WAIT_PARITY(mb_full + s_cur * 8, fp);
            ldsm_ks0(tiles + (uint32_t)s_cur * STAGE_BYTES);
        }
    }

    // ---- epilogue: y = scale[n] * acc + bias[n] ----
    const int ncol = n0 + 64 * wn + 2 * (lane & 3);
    const float* scn = scale + ncol;
    const float* bin = bias + ncol;
    #pragma unroll
    for (int mb = 0; mb < 4; ++mb) {
        const int mr0 = m0 + 64 * wm + 16 * mb + (lane >> 2);
        const int mr1 = mr0 + 8;
        float* o0 = out + (size_t)mr0 * NDIM + ncol;
        float* o1 = out + (size_t)mr1 * NDIM + ncol;
        #pragma unroll
        for (int nt = 0; nt < 8; ++nt) {
            const float2 ws = *(const float2*)(scn + 8 * nt);
            const float2 bb = *(const float2*)(bin + 8 * nt);
            float2 v0, v1;
            v0.x = ws.x * acc[mb][nt][0] + bb.x;
            v0.y = ws.y * acc[mb][nt][1] + bb.y;
            v1.x = ws.x * acc[mb][nt][2] + bb.x;
            v1.y = ws.y * acc[mb][nt][3] + bb.y;
            *(float2*)(o0 + 8 * nt) = v0;
            *(float2*)(o1 + 8 * nt) = v1;
        }
    }
}

// ---------------- launcher ----------------
extern "C" void kernel_launch(void* const* d_in, const int* in_sizes, int n_in,
                              void* d_out, int out_size) {
    const float* x     = (const float*)d_in[0];
    const int*   w     = (const int*)d_in[1];
    const float* scale = (const float*)d_in[2];
    const float* bias  = (const float*)d_in[3];
    float* out = (float*)d_out;

    cudaFuncSetAttribute(qgemm_kernel, cudaFuncAttributeMaxDynamicSharedMemorySize, SMEM_BYTES);

    cvt_kernel<<<4096, 256>>>(x, w);

    dim3 grid(NDIM / NT, MDIM / MT);   // (32, 64) = 2048 CTAs
    qgemm_kernel<<<grid, 128, SMEM_BYTES>>>(scale, bias, out);
}

// round 16
// speedup vs baseline: 1.0534x; 1.0381x over previous
#include <cuda_runtime.h>
#include <cuda_fp16.h>
#include <cstdint>
#include <cstddef>

// ---------------- problem sizes ----------------
#define MDIM 8192
#define NDIM 4096
#define KDIM 4096
#define MT 128          // CTA tile M
#define NT 128          // CTA tile N
#define KC 64           // K elements per chunk (fp16 -> 128B rows)
#define NCHUNK (KDIM / KC)          // 64
#define STAGES 3
#define A_TILE 16384                // 128 rows x 128B
#define B_TILE 16384                // 128 rows x 128B
#define STAGE_BYTES (A_TILE + B_TILE)       // 32768
#define SMEM_BYTES (STAGES * STAGE_BYTES)   // 98304 -> 2 CTAs/SM

// ---------------- device scratch (no allocation allowed) ----------------
__device__ __align__(128) __half g_X[(size_t)MDIM * KDIM];
__device__ __align__(128) __half g_W[(size_t)NDIM * KDIM];

// ---------------- PTX helpers (base sm_103 target only) -------------------
static __device__ __forceinline__ uint32_t smem_u32(const void* p) {
    uint32_t a;
    asm("{ .reg .u64 t; cvta.to.shared.u64 t, %1; cvt.u32.u64 %0, t; }" : "=r"(a) : "l"(p));
    return a;
}

#define CP16(dst, src) \
    asm volatile("cp.async.cg.shared.global [%0], [%1], 16;" :: "r"((uint32_t)(dst)), "l"(src) : "memory")
#define CP_COMMIT() asm volatile("cp.async.commit_group;" ::: "memory")
#define CP_WAIT(n)  asm volatile("cp.async.wait_group %0;" :: "n"(n) : "memory")

#define LDSM4(r0, r1, r2, r3, addr) \
    asm volatile("ldmatrix.sync.aligned.m8n8.x4.shared.b16 {%0,%1,%2,%3}, [%4];" \
                 : "=r"(r0), "=r"(r1), "=r"(r2), "=r"(r3) : "r"(addr))

// f16 MMA, fp32 accumulate: D[16x8] += A[16x16] * B[16x8]
#define MMA_F16(d, a0, a1, a2, a3, b0, b1) \
    asm volatile("mma.sync.aligned.m16n8k16.row.col.f32.f16.f16.f32 " \
                 "{%0,%1,%2,%3}, {%4,%5,%6,%7}, {%8,%9}, {%0,%1,%2,%3};" \
                 : "+f"((d)[0]), "+f"((d)[1]), "+f"((d)[2]), "+f"((d)[3]) \
                 : "r"(a0), "r"(a1), "r"(a2), "r"(a3), "r"(b0), "r"(b1))

// ---------------- fused prepass: x fp32->fp16, w int32->fp16 --------------
// 8 elements per thread per iteration: two 16B loads -> one 16B store.
#define NX8 ((size_t)MDIM * KDIM / 8)
#define NW8 ((size_t)NDIM * KDIM / 8)
__global__ void __launch_bounds__(256) cvt_kernel(const float* __restrict__ x,
                                                  const int* __restrict__ w) {
    const float4* __restrict__ x4 = (const float4*)x;
    const int4* __restrict__ w4 = (const int4*)w;
    uint4* __restrict__ dx = (uint4*)g_X;
    uint4* __restrict__ dw = (uint4*)g_W;
    const size_t total = NX8 + NW8;
    size_t stride = (size_t)gridDim.x * blockDim.x;
    for (size_t i = (size_t)blockIdx.x * blockDim.x + threadIdx.x; i < total; i += stride) {
        uint4 p;
        if (i < NX8) {
            float4 v0 = x4[2 * i];
            float4 v1 = x4[2 * i + 1];
            p.x = (uint32_t)__half_as_ushort(__float2half_rn(v0.x)) |
                  ((uint32_t)__half_as_ushort(__float2half_rn(v0.y)) << 16);
            p.y = (uint32_t)__half_as_ushort(__float2half_rn(v0.z)) |
                  ((uint32_t)__half_as_ushort(__float2half_rn(v0.w)) << 16);
            p.z = (uint32_t)__half_as_ushort(__float2half_rn(v1.x)) |
                  ((uint32_t)__half_as_ushort(__float2half_rn(v1.y)) << 16);
            p.w = (uint32_t)__half_as_ushort(__float2half_rn(v1.z)) |
                  ((uint32_t)__half_as_ushort(__float2half_rn(v1.w)) << 16);
            dx[i] = p;
        } else {
            const size_t j = i - NX8;
            int4 v0 = w4[2 * j];
            int4 v1 = w4[2 * j + 1];
            p.x = (uint32_t)__half_as_ushort(__int2half_rn(v0.x)) |
                  ((uint32_t)__half_as_ushort(__int2half_rn(v0.y)) << 16);
            p.y = (uint32_t)__half_as_ushort(__int2half_rn(v0.z)) |
                  ((uint32_t)__half_as_ushort(__int2half_rn(v0.w)) << 16);
            p.z = (uint32_t)__half_as_ushort(__int2half_rn(v1.x)) |
                  ((uint32_t)__half_as_ushort(__int2half_rn(v1.y)) << 16);
            p.w = (uint32_t)__half_as_ushort(__int2half_rn(v1.z)) |
                  ((uint32_t)__half_as_ushort(__int2half_rn(v1.w)) << 16);
            dw[j] = p;
        }
    }
}

// ---------------- main GEMM: mma.sync f16 (f32 acc), cp.async 3-stage -----
// 128 threads = 4 warps. CTA tile 128(M) x 128(N); warp tile 64(M) x 64(N).
// 2 CTAs/SM. Cross-chunk ks0 fragment prefetch (R13) + ks1 ldmatrix issued
// BEFORE the produce burst, reusing the ks0 fragment registers (dead after
// MMA issue) so ks1's LDS latency drains under the burst + MMA backlog.
__global__ void __launch_bounds__(128, 2) qgemm_kernel(
    const float* __restrict__ scale,
    const float* __restrict__ bias,
    float* __restrict__ out
) {
    extern __shared__ char smem[];
    const uint32_t sbase = smem_u32(smem);
    const int tid = threadIdx.x;
    const int m0 = blockIdx.y * MT;
    const int n0 = blockIdx.x * NT;

    const int lane = tid & 31;
    const int wid = tid >> 5;
    const int wm = wid & 1;      // M half (64 rows)
    const int wn = wid >> 1;     // N half (64 cols)

    // gmem byte-bases (row stride = KDIM * 2 bytes = 8192 = 1<<13)
    const char* pX = (const char*)g_X + ((size_t)m0 << 13);
    const char* pW = (const char*)g_W + ((size_t)n0 << 13);

    // ldmatrix address components
    const int rA = 64 * wm + (lane & 7) + ((lane >> 3) & 1) * 8;
    const int kaddA = ((lane >> 4) & 1) * 16;
    const uint32_t xmA = (uint32_t)((lane & 7) << 4);
    const int nrb = 64 * wn + (lane & 7) + ((lane >> 4) & 1) * 8;
    const int kaddB = ((lane >> 3) & 1) * 16;
    const uint32_t xmB = (uint32_t)((lane & 7) << 4);
    const uint32_t kA0 = ((uint32_t)kaddA) ^ xmA;
    const uint32_t kB0 = ((uint32_t)kaddB) ^ xmB;

    float acc[4][8][4];
    #pragma unroll
    for (int a = 0; a < 4; ++a)
        #pragma unroll
        for (int b = 0; b < 8; ++b)
            #pragma unroll
            for (int c = 0; c < 4; ++c) acc[a][b][c] = 0.0f;

    // ---- stage loader: A 16KB + B 16KB, 8 granule-pairs/thread ----
    auto load_stage = [&](int stg, int c) {
        const uint32_t st = sbase + (uint32_t)stg * STAGE_BYTES;
        const uint32_t ko = (uint32_t)c << 7;       // c * 128 bytes along K
        #pragma unroll
        for (int i = 0; i < 8; ++i) {               // A + B: rows 0..127 each
            const int g = tid + i * 128;
            const int row = g >> 3;
            const int col = (g & 7) << 4;
            const uint32_t soff = (uint32_t)(row * 128) + ((uint32_t)col ^ (uint32_t)((row & 7) << 4));
            const size_t goff = ((size_t)row << 13) + ko + col;
            CP16(st + soff,          pX + goff);
            CP16(st + A_TILE + soff, pW + goff);
        }
    };

    uint32_t af[4][4];
    uint32_t bf[4][4];

    // fragment loader for k-step ks from a given stage base
    auto ldsm_ks = [&](uint32_t st, int ks) {
        const uint32_t aA = st + (uint32_t)(rA * 128);
        const uint32_t aB = st + A_TILE + (uint32_t)(nrb * 128);
        const uint32_t kA = ((uint32_t)(ks * 32 + kaddA)) ^ xmA;
        const uint32_t kB = ((uint32_t)(ks * 32 + kaddB)) ^ xmB;
        #pragma unroll
        for (int mb = 0; mb < 4; ++mb)
            LDSM4(af[mb][0], af[mb][1], af[mb][2], af[mb][3],
                  aA + (uint32_t)(mb * 16 * 128) + kA);
        #pragma unroll
        for (int p = 0; p < 4; ++p)
            LDSM4(bf[p][0], bf[p][1], bf[p][2], bf[p][3],
                  aB + (uint32_t)(p * 16 * 128) + kB);
    };

    // all 32 MMAs for the currently loaded fragments
    auto mma_all = [&]() {
        #pragma unroll
        for (int mb = 0; mb < 4; ++mb) {
            #pragma unroll
            for (int nt = 0; nt < 8; ++nt) {
                const uint32_t b0 = bf[nt >> 1][(nt & 1) * 2];
                const uint32_t b1 = bf[nt >> 1][(nt & 1) * 2 + 1];
                MMA_F16(acc[mb][nt], af[mb][0], af[mb][1], af[mb][2], af[mb][3], b0, b1);
            }
        }
    };

    // ---- prologue: stages 0,1; prefetch ks0 of chunk 0 ----
    load_stage(0, 0); CP_COMMIT();
    load_stage(1, 1); CP_COMMIT();
    CP_WAIT(1);
    __syncthreads();
    ldsm_ks(sbase, 0);

    // ---- mainloop ----
    int s_cur = 0;          // stage of chunk c
    int s_nxt = 2;          // stage to fill with chunk c+2
    for (int c = 0; c < NCHUNK; ++c) {
        const uint32_t st = sbase + (uint32_t)s_cur * STAGE_BYTES;

        // ks0 MMAs from prefetched fragments (pipe fills immediately)
        mma_all();

        // ks1 ldmatrix into the just-freed fragment registers: its LDS
        // latency drains under the produce burst issue + ks0 MMA backlog
        ldsm_ks(st, 1);

        // produce burst under the ks0 MMA backlog
        if (c + 2 < NCHUNK) load_stage(s_nxt, c + 2);
        CP_COMMIT();

        // ks1 MMAs
        mma_all();

        // ks2, ks3
        ldsm_ks(st, 2);
        mma_all();
        ldsm_ks(st, 3);
        mma_all();

        // ---- end of iter: guarantee chunk c+1 data, then prefetch its ks0
        CP_WAIT(1);
        __syncthreads();
        s_cur = (s_cur == 2) ? 0 : s_cur + 1;
        s_nxt = (s_nxt == 2) ? 0 : s_nxt + 1;
        if (c + 1 < NCHUNK)
            ldsm_ks(sbase + (uint32_t)s_cur * STAGE_BYTES, 0);
    }

    // ---- epilogue: y = scale[n] * acc + bias[n] ----
    const int ncol = n0 + 64 * wn + 2 * (lane & 3);
    const float* scn = scale + ncol;
    const float* bin = bias + ncol;
    #pragma unroll
    for (int mb = 0; mb < 4; ++mb) {
        const int mr0 = m0 + 64 * wm + 16 * mb + (lane >> 2);
        const int mr1 = mr0 + 8;
        float* o0 = out + (size_t)mr0 * NDIM + ncol;
        float* o1 = out + (size_t)mr1 * NDIM + ncol;
        #pragma unroll
        for (int nt = 0; nt < 8; ++nt) {
            const float2 ws = *(const float2*)(scn + 8 * nt);
            const float2 bb = *(const float2*)(bin + 8 * nt);
            float2 v0, v1;
            v0.x = ws.x * acc[mb][nt][0] + bb.x;
            v0.y = ws.y * acc[mb][nt][1] + bb.y;
            v1.x = ws.x * acc[mb][nt][2] + bb.x;
            v1.y = ws.y * acc[mb][nt][3] + bb.y;
            *(float2*)(o0 + 8 * nt) = v0;
            *(float2*)(o1 + 8 * nt) = v1;
        }
    }
}

// ---------------- launcher ----------------
extern "C" void kernel_launch(void* const* d_in, const int* in_sizes, int n_in,
                              void* d_out, int out_size) {
    const float* x     = (const float*)d_in[0];
    const int*   w     = (const int*)d_in[1];
    const float* scale = (const float*)d_in[2];
    const float* bias  = (const float*)d_in[3];
    float* out = (float*)d_out;

    cudaFuncSetAttribute(qgemm_kernel, cudaFuncAttributeMaxDynamicSharedMemorySize, SMEM_BYTES);

    cvt_kernel<<<4096, 256>>>(x, w);

    dim3 grid(NDIM / NT, MDIM / MT);   // (32, 64) = 2048 CTAs
    qgemm_kernel<<<grid, 128, SMEM_BYTES>>>(scale, bias, out);
}

// round 17
// speedup vs baseline: 1.0660x; 1.0120x over previous
#include <cuda_runtime.h>
#include <cuda_fp16.h>
#include <cstdint>
#include <cstddef>

// ---------------- problem sizes ----------------
#define MDIM 8192
#define NDIM 4096
#define KDIM 4096
#define MT 128          // CTA tile M
#define NT 128          // CTA tile N
#define KC 64           // K elements per chunk (fp16 -> 128B rows)
#define NCHUNK (KDIM / KC)          // 64
#define STAGES 3
#define A_TILE 16384                // 128 rows x 128B
#define B_TILE 16384                // 128 rows x 128B
#define STAGE_BYTES (A_TILE + B_TILE)       // 32768
#define SMEM_BYTES (STAGES * STAGE_BYTES)   // 98304 -> 2 CTAs/SM

// ---------------- device scratch (no allocation allowed) ----------------
__device__ __align__(128) __half g_X[(size_t)MDIM * KDIM];
__device__ __align__(128) __half g_W[(size_t)NDIM * KDIM];

// ---------------- PTX helpers (base sm_103 target only) -------------------
static __device__ __forceinline__ uint32_t smem_u32(const void* p) {
    uint32_t a;
    asm("{ .reg .u64 t; cvta.to.shared.u64 t, %1; cvt.u32.u64 %0, t; }" : "=r"(a) : "l"(p));
    return a;
}

#define CP16(dst, src) \
    asm volatile("cp.async.cg.shared.global [%0], [%1], 16;" :: "r"((uint32_t)(dst)), "l"(src) : "memory")
#define CP_COMMIT() asm volatile("cp.async.commit_group;" ::: "memory")
#define CP_WAIT(n)  asm volatile("cp.async.wait_group %0;" :: "n"(n) : "memory")

#define LDSM4(r0, r1, r2, r3, addr) \
    asm volatile("ldmatrix.sync.aligned.m8n8.x4.shared.b16 {%0,%1,%2,%3}, [%4];" \
                 : "=r"(r0), "=r"(r1), "=r"(r2), "=r"(r3) : "r"(addr))

// f16 MMA, fp32 accumulate: D[16x8] += A[16x16] * B[16x8]
#define MMA_F16(d, a0, a1, a2, a3, b0, b1) \
    asm volatile("mma.sync.aligned.m16n8k16.row.col.f32.f16.f16.f32 " \
                 "{%0,%1,%2,%3}, {%4,%5,%6,%7}, {%8,%9}, {%0,%1,%2,%3};" \
                 : "+f"((d)[0]), "+f"((d)[1]), "+f"((d)[2]), "+f"((d)[3]) \
                 : "r"(a0), "r"(a1), "r"(a2), "r"(a3), "r"(b0), "r"(b1))

// ---------------- fused prepass: x fp32->fp16, w int32->fp16 --------------
// 16 elements per thread per iteration: four 16B loads -> two 16B stores.
// Wide per-iteration MLP (4 independent loads) keeps the LDG queue deep.
#define NX16 ((size_t)MDIM * KDIM / 16)
#define NW16 ((size_t)NDIM * KDIM / 16)
static __device__ __forceinline__ uint32_t pack2h_f(float a, float b) {
    return (uint32_t)__half_as_ushort(__float2half_rn(a)) |
           ((uint32_t)__half_as_ushort(__float2half_rn(b)) << 16);
}
static __device__ __forceinline__ uint32_t pack2h_i(int a, int b) {
    return (uint32_t)__half_as_ushort(__int2half_rn(a)) |
           ((uint32_t)__half_as_ushort(__int2half_rn(b)) << 16);
}
__global__ void __launch_bounds__(256) cvt_kernel(const float* __restrict__ x,
                                                  const int* __restrict__ w) {
    const float4* __restrict__ x4 = (const float4*)x;
    const int4* __restrict__ w4 = (const int4*)w;
    uint4* __restrict__ dx = (uint4*)g_X;
    uint4* __restrict__ dw = (uint4*)g_W;
    const size_t total = NX16 + NW16;
    size_t stride = (size_t)gridDim.x * blockDim.x;
    for (size_t i = (size_t)blockIdx.x * blockDim.x + threadIdx.x; i < total; i += stride) {
        if (i < NX16) {
            float4 v0 = x4[4 * i];
            float4 v1 = x4[4 * i + 1];
            float4 v2 = x4[4 * i + 2];
            float4 v3 = x4[4 * i + 3];
            uint4 p0, p1;
            p0.x = pack2h_f(v0.x, v0.y); p0.y = pack2h_f(v0.z, v0.w);
            p0.z = pack2h_f(v1.x, v1.y); p0.w = pack2h_f(v1.z, v1.w);
            p1.x = pack2h_f(v2.x, v2.y); p1.y = pack2h_f(v2.z, v2.w);
            p1.z = pack2h_f(v3.x, v3.y); p1.w = pack2h_f(v3.z, v3.w);
            dx[2 * i] = p0;
            dx[2 * i + 1] = p1;
        } else {
            const size_t j = i - NX16;
            int4 v0 = w4[4 * j];
            int4 v1 = w4[4 * j + 1];
            int4 v2 = w4[4 * j + 2];
            int4 v3 = w4[4 * j + 3];
            uint4 p0, p1;
            p0.x = pack2h_i(v0.x, v0.y); p0.y = pack2h_i(v0.z, v0.w);
            p0.z = pack2h_i(v1.x, v1.y); p0.w = pack2h_i(v1.z, v1.w);
            p1.x = pack2h_i(v2.x, v2.y); p1.y = pack2h_i(v2.z, v2.w);
            p1.z = pack2h_i(v3.x, v3.y); p1.w = pack2h_i(v3.z, v3.w);
            dw[2 * j] = p0;
            dw[2 * j + 1] = p1;
        }
    }
}

// ---------------- main GEMM: mma.sync f16 (f32 acc), cp.async 3-stage -----
// R13 verbatim (measured optimum of this family): 128 threads = 4 warps,
// CTA tile 128x128, warp tile 64x64, 2 CTAs/SM. Cross-chunk ks0 fragment
// prefetch: each iteration ends with CP_WAIT+barrier followed by the NEXT
// chunk's ks0 ldmatrix under the ks3 MMA backlog; the produce burst sits
// between ks0 LDSM-prefetch consumption and ks1 in the proven R10/R13 slot.
__global__ void __launch_bounds__(128, 2) qgemm_kernel(
    const float* __restrict__ scale,
    const float* __restrict__ bias,
    float* __restrict__ out
) {
    extern __shared__ char smem[];
    const uint32_t sbase = smem_u32(smem);
    const int tid = threadIdx.x;
    const int m0 = blockIdx.y * MT;
    const int n0 = blockIdx.x * NT;

    const int lane = tid & 31;
    const int wid = tid >> 5;
    const int wm = wid & 1;      // M half (64 rows)
    const int wn = wid >> 1;     // N half (64 cols)

    // gmem byte-bases (row stride = KDIM * 2 bytes = 8192 = 1<<13)
    const char* pX = (const char*)g_X + ((size_t)m0 << 13);
    const char* pW = (const char*)g_W + ((size_t)n0 << 13);

    // ldmatrix address components
    const int rA = 64 * wm + (lane & 7) + ((lane >> 3) & 1) * 8;
    const int kaddA = ((lane >> 4) & 1) * 16;
    const uint32_t xmA = (uint32_t)((lane & 7) << 4);
    const int nrb = 64 * wn + (lane & 7) + ((lane >> 4) & 1) * 8;
    const int kaddB = ((lane >> 3) & 1) * 16;
    const uint32_t xmB = (uint32_t)((lane & 7) << 4);
    const uint32_t kA0 = ((uint32_t)kaddA) ^ xmA;
    const uint32_t kB0 = ((uint32_t)kaddB) ^ xmB;

    float acc[4][8][4];
    #pragma unroll
    for (int a = 0; a < 4; ++a)
        #pragma unroll
        for (int b = 0; b < 8; ++b)
            #pragma unroll
            for (int c = 0; c < 4; ++c) acc[a][b][c] = 0.0f;

    // ---- stage loader: A 16KB + B 16KB, 8 granule-pairs/thread ----
    auto load_stage = [&](int stg, int c) {
        const uint32_t st = sbase + (uint32_t)stg * STAGE_BYTES;
        const uint32_t ko = (uint32_t)c << 7;       // c * 128 bytes along K
        #pragma unroll
        for (int i = 0; i < 8; ++i) {               // A + B: rows 0..127 each
            const int g = tid + i * 128;
            const int row = g >> 3;
            const int col = (g & 7) << 4;
            const uint32_t soff = (uint32_t)(row * 128) + ((uint32_t)col ^ (uint32_t)((row & 7) << 4));
            const size_t goff = ((size_t)row << 13) + ko + col;
            CP16(st + soff,          pX + goff);
            CP16(st + A_TILE + soff, pW + goff);
        }
    };

    uint32_t af[4][4];
    uint32_t bf[4][4];

    // ks0 fragment loader from a given stage base
    auto ldsm_ks0 = [&](uint32_t st) {
        const uint32_t aA = st + (uint32_t)(rA * 128);
        const uint32_t aB = st + A_TILE + (uint32_t)(nrb * 128);
        #pragma unroll
        for (int mb = 0; mb < 4; ++mb)
            LDSM4(af[mb][0], af[mb][1], af[mb][2], af[mb][3],
                  aA + (uint32_t)(mb * 16 * 128) + kA0);
        #pragma unroll
        for (int p = 0; p < 4; ++p)
            LDSM4(bf[p][0], bf[p][1], bf[p][2], bf[p][3],
                  aB + (uint32_t)(p * 16 * 128) + kB0);
    };

    // ---- prologue: stages 0,1; prefetch ks0 of chunk 0 ----
    load_stage(0, 0); CP_COMMIT();
    load_stage(1, 1); CP_COMMIT();
    CP_WAIT(1);
    __syncthreads();
    ldsm_ks0(sbase);

    // ---- mainloop ----
    int s_cur = 0;          // stage of chunk c
    int s_nxt = 2;          // stage to fill with chunk c+2
    for (int c = 0; c < NCHUNK; ++c) {
        const uint32_t st = sbase + (uint32_t)s_cur * STAGE_BYTES;
        const uint32_t aA = st + (uint32_t)(rA * 128);
        const uint32_t aB = st + A_TILE + (uint32_t)(nrb * 128);

        // ---- ks0 MMAs from prefetched fragments (pipe fills immediately)
        #pragma unroll
        for (int mb = 0; mb < 4; ++mb) {
            #pragma unroll
            for (int nt = 0; nt < 8; ++nt) {
                const uint32_t b0 = bf[nt >> 1][(nt & 1) * 2];
                const uint32_t b1 = bf[nt >> 1][(nt & 1) * 2 + 1];
                MMA_F16(acc[mb][nt], af[mb][0], af[mb][1], af[mb][2], af[mb][3], b0, b1);
            }
        }

        // ---- produce burst under the ks0 MMA backlog
        if (c + 2 < NCHUNK) load_stage(s_nxt, c + 2);
        CP_COMMIT();

        // ---- k-steps 1..3
        #pragma unroll
        for (int ks = 1; ks < 4; ++ks) {
            const uint32_t kA = ((uint32_t)(ks * 32 + kaddA)) ^ xmA;
            const uint32_t kB = ((uint32_t)(ks * 32 + kaddB)) ^ xmB;
            #pragma unroll
            for (int mb = 0; mb < 4; ++mb)
                LDSM4(af[mb][0], af[mb][1], af[mb][2], af[mb][3],
                      aA + (uint32_t)(mb * 16 * 128) + kA);
            #pragma unroll
            for (int p = 0; p < 4; ++p)
                LDSM4(bf[p][0], bf[p][1], bf[p][2], bf[p][3],
                      aB + (uint32_t)(p * 16 * 128) + kB);
            #pragma unroll
            for (int mb = 0; mb < 4; ++mb) {
                #pragma unroll
                for (int nt = 0; nt < 8; ++nt) {
                    const uint32_t b0 = bf[nt >> 1][(nt & 1) * 2];
                    const uint32_t b1 = bf[nt >> 1][(nt & 1) * 2 + 1];
                    MMA_F16(acc[mb][nt], af[mb][0], af[mb][1], af[mb][2], af[mb][3], b0, b1);
                }
            }
        }

        // ---- end of iter: guarantee chunk c+1 data, then prefetch its ks0
        // (ks3 MMA backlog covers the wait+barrier+LDSM latency)
        CP_WAIT(1);
        __syncthreads();
        s_cur = (s_cur == 2) ? 0 : s_cur + 1;
        s_nxt = (s_nxt == 2) ? 0 : s_nxt + 1;
        if (c + 1 < NCHUNK)
            ldsm_ks0(sbase + (uint32_t)s_cur * STAGE_BYTES);
    }

    // ---- epilogue: y = scale[n] * acc + bias[n] ----
    const int ncol = n0 + 64 * wn + 2 * (lane & 3);
    const float* scn = scale + ncol;
    const float* bin = bias + ncol;
    #pragma unroll
    for (int mb = 0; mb < 4; ++mb) {
        const int mr0 = m0 + 64 * wm + 16 * mb + (lane >> 2);
        const int mr1 = mr0 + 8;
        float* o0 = out + (size_t)mr0 * NDIM + ncol;
        float* o1 = out + (size_t)mr1 * NDIM + ncol;
        #pragma unroll
        for (int nt = 0; nt < 8; ++nt) {
            const float2 ws = *(const float2*)(scn + 8 * nt);
            const float2 bb = *(const float2*)(bin + 8 * nt);
            float2 v0, v1;
            v0.x = ws.x * acc[mb][nt][0] + bb.x;
            v0.y = ws.y * acc[mb][nt][1] + bb.y;
            v1.x = ws.x * acc[mb][nt][2] + bb.x;
            v1.y = ws.y * acc[mb][nt][3] + bb.y;
            *(float2*)(o0 + 8 * nt) = v0;
            *(float2*)(o1 + 8 * nt) = v1;
        }
    }
}

// ---------------- launcher ----------------
extern "C" void kernel_launch(void* const* d_in, const int* in_sizes, int n_in,
                              void* d_out, int out_size) {
    const float* x     = (const float*)d_in[0];
    const int*   w     = (const int*)d_in[1];
    const float* scale = (const float*)d_in[2];
    const float* bias  = (const float*)d_in[3];
    float* out = (float*)d_out;

    cudaFuncSetAttribute(qgemm_kernel, cudaFuncAttributeMaxDynamicSharedMemorySize, SMEM_BYTES);

    cvt_kernel<<<4096, 256>>>(x, w);

    dim3 grid(NDIM / NT, MDIM / MT);   // (32, 64) = 2048 CTAs
    qgemm_kernel<<<grid, 128, SMEM_BYTES>>>(scale, bias, out);
}